// round 3
// baseline (speedup 1.0000x reference)
#include <cuda_runtime.h>
#include <cstdint>

// Problem dims: B=4, S=4096, D=4096, E=64, K=2
#define NTOK 16384
#define DDIM 4096
#define NEXP 64
#define TPC  128                 // tokens per CTA
#define NCTA (NTOK / TPC)        // 128
#define THREADS 256
#define KC   64                  // K per chunk
#define NCHUNK (DDIM / KC)       // 64

// Output layout (flattened f32): idx[2N], scores[2N], probs[64N], zloss[1], imp[64], load[64]
#define OFF_IDX     0
#define OFF_SCORES  (NTOK * 2)
#define OFF_PROBS   (NTOK * 4)
#define OFF_ZLOSS   (NTOK * 4 + NTOK * NEXP)
#define OFF_IMP     (OFF_ZLOSS + 1)
#define OFF_LOAD    (OFF_IMP + NEXP)

// smem: B tiles only. row pitch 144B (128B data + 16B pad -> conflict-free ldmatrix)
#define BPITCH 144
#define LEVSZ  (64 * BPITCH)         // 9216
#define BUF3   (3 * LEVSZ)           // 27648 per buffer
#define SMEM_TOTAL (2 * BUF3)        // 55296

// Scratch globals (allocation-free rule)
__device__ unsigned short g_Wh[NEXP * DDIM];
__device__ unsigned short g_Wm[NEXP * DDIM];
__device__ unsigned short g_Wl[NEXP * DDIM];
__device__ float g_acc[2 * NEXP + 1];
__device__ unsigned int g_done;

// ---------------------------------------------------------------------------
__device__ __forceinline__ uint32_t smem_u32(const void* p) {
    uint32_t a;
    asm("{ .reg .u64 t; cvta.to.shared.u64 t, %1; cvt.u32.u64 %0, t; }" : "=r"(a) : "l"(p));
    return a;
}
// packed bf16x2: low16 = bf16(lo), high16 = bf16(hi)
__device__ __forceinline__ unsigned cvt2bf(float lo, float hi) {
    unsigned r;
    asm("cvt.rn.bf16x2.f32 %0, %1, %2;" : "=r"(r) : "f"(hi), "f"(lo));
    return r;
}
__device__ __forceinline__ float bf_lo(unsigned p) { return __uint_as_float(p << 16); }
__device__ __forceinline__ float bf_hi(unsigned p) { return __uint_as_float(p & 0xffff0000u); }

// split one float2 into 3 bf16x2 levels (round-to-nearest at each stage)
__device__ __forceinline__ void splitA(float2 v, unsigned& h, unsigned& m, unsigned& l) {
    h = cvt2bf(v.x, v.y);
    float r1x = v.x - bf_lo(h), r1y = v.y - bf_hi(h);
    m = cvt2bf(r1x, r1y);
    float r2x = r1x - bf_lo(m), r2y = r1y - bf_hi(m);
    l = cvt2bf(r2x, r2y);
}

#define LDSM4(R, a) \
    asm volatile("ldmatrix.sync.aligned.m8n8.x4.shared.b16 {%0,%1,%2,%3}, [%4];" \
        : "=r"((R)[0]), "=r"((R)[1]), "=r"((R)[2]), "=r"((R)[3]) : "r"(a))

#define MMA(C, A, B0, B1) \
    asm volatile("mma.sync.aligned.m16n8k16.row.col.f32.bf16.bf16.f32 " \
        "{%0,%1,%2,%3}, {%4,%5,%6,%7}, {%8,%9}, {%0,%1,%2,%3};" \
        : "+f"((C)[0]), "+f"((C)[1]), "+f"((C)[2]), "+f"((C)[3]) \
        : "r"((A)[0]), "r"((A)[1]), "r"((A)[2]), "r"((A)[3]), "r"(B0), "r"(B1))

__device__ __forceinline__ bool better(float v1, int i1, float v2, int i2) {
    return (v1 > v2) || (v1 == v2 && i1 < i2);
}

// ---------------------------------------------------------------------------
// Kernel 1: split W into 3 bf16 levels, zero accumulators
// ---------------------------------------------------------------------------
__global__ void prep_kernel(const float* __restrict__ W) {
    int i = blockIdx.x * 256 + threadIdx.x;
    if (i < NEXP * DDIM) {
        float w = W[i];
        unsigned h = cvt2bf(w, 0.0f);
        float r1 = w - bf_lo(h);
        unsigned m = cvt2bf(r1, 0.0f);
        float r2 = r1 - bf_lo(m);
        unsigned l = cvt2bf(r2, 0.0f);
        g_Wh[i] = (unsigned short)h;
        g_Wm[i] = (unsigned short)m;
        g_Wl[i] = (unsigned short)l;
    }
    if (i < 2 * NEXP + 1) g_acc[i] = 0.0f;
    if (i == 0) g_done = 0u;
}

// ---------------------------------------------------------------------------
// per-token-row routing epilogue (quad = 4 lanes owning one row)
// ---------------------------------------------------------------------------
__device__ __forceinline__ void row_epilogue(const float v[16], float p[16],
                                             int token, int qc, int lane,
                                             float* __restrict__ out,
                                             float* s_cnt, float& zz) {
    // quad max
    float mx = v[0];
#pragma unroll
    for (int i = 1; i < 16; ++i) mx = fmaxf(mx, v[i]);
    mx = fmaxf(mx, __shfl_xor_sync(0xffffffffu, mx, 1));
    mx = fmaxf(mx, __shfl_xor_sync(0xffffffffu, mx, 2));
    // quad sum of exp
    float s = 0.0f;
#pragma unroll
    for (int i = 0; i < 16; ++i) { p[i] = __expf(v[i] - mx); s += p[i]; }
    s += __shfl_xor_sync(0xffffffffu, s, 1);
    s += __shfl_xor_sync(0xffffffffu, s, 2);
    const float inv = 1.0f / s;
#pragma unroll
    for (int i = 0; i < 16; ++i) p[i] *= inv;
    // probs out: cols j*8 + qc + {0,1}
    float* po = out + OFF_PROBS + (size_t)token * NEXP;
#pragma unroll
    for (int j = 0; j < 8; ++j)
        *reinterpret_cast<float2*>(po + j * 8 + qc) = make_float2(p[2 * j], p[2 * j + 1]);
    // local top-2 (ascending col order; strict > keeps lowest index on ties)
    float av = -3.4e38f, bv = -3.4e38f; int ai = 0, bi = 0;
#pragma unroll
    for (int j = 0; j < 8; ++j)
#pragma unroll
        for (int i = 0; i < 2; ++i) {
            float val = v[j * 2 + i];
            int col = j * 8 + qc + i;
            if (val > av)      { bv = av; bi = ai; av = val; ai = col; }
            else if (val > bv) { bv = val; bi = col; }
        }
    // quad merge
#pragma unroll
    for (int o = 1; o <= 2; o <<= 1) {
        float av2 = __shfl_xor_sync(0xffffffffu, av, o);
        int   ai2 = __shfl_xor_sync(0xffffffffu, ai, o);
        float bv2 = __shfl_xor_sync(0xffffffffu, bv, o);
        int   bi2 = __shfl_xor_sync(0xffffffffu, bi, o);
        if (better(av2, ai2, av, ai)) {
            bool s2 = better(bv2, bi2, av, ai);
            float nbv = s2 ? bv2 : av; int nbi = s2 ? bi2 : ai;
            av = av2; ai = ai2; bv = nbv; bi = nbi;
        } else if (better(av2, ai2, bv, bi)) { bv = av2; bi = ai2; }
    }
    if ((lane & 3) == 0) {
        float ex  = __expf(bv - av);
        float sc0 = 1.0f / (1.0f + ex);
        out[OFF_IDX + token * 2]        = (float)ai;
        out[OFF_IDX + token * 2 + 1]    = (float)bi;
        out[OFF_SCORES + token * 2]     = sc0;
        out[OFF_SCORES + token * 2 + 1] = ex * sc0;
        atomicAdd(&s_cnt[ai], 1.0f);
        atomicAdd(&s_cnt[bi], 1.0f);
    }
    float z = mx + __logf(s);
    zz += z * z;   // identical across quad; only lane%4==0 chain is consumed
}

// ---------------------------------------------------------------------------
// Kernel 2: fused 6-way bf16-split GEMM (mma.sync) + routing epilogue
// ---------------------------------------------------------------------------
__global__ void __launch_bounds__(THREADS, 1)
router_kernel(const float* __restrict__ x, float* __restrict__ out) {
    extern __shared__ __align__(16) char smem[];
    const uint32_t sb = smem_u32(smem);
    const int tid = threadIdx.x, w = tid >> 5, lane = tid & 31;
    const int g = lane >> 2, qc = (lane & 3) * 2;

    const int token_r0 = blockIdx.x * TPC + w * 16 + g;   // row g; row g+8 = +8
    const float* xr0 = x + (size_t)token_r0 * DDIM;
    const float* xr1 = xr0 + (size_t)8 * DDIM;

    // B cooperative-load mapping: 2 slots/thread, row = slot>>3, seg = slot&7
    const int brow0 = tid >> 3, bseg = tid & 7;
    const int brow1 = brow0 + 32;
    const uint4* pWh = reinterpret_cast<const uint4*>(g_Wh);
    const uint4* pWm = reinterpret_cast<const uint4*>(g_Wm);
    const uint4* pWl = reinterpret_cast<const uint4*>(g_Wl);
    const size_t bofs0 = (size_t)brow0 * 512 + bseg;      // uint4 units
    const size_t bofs1 = (size_t)brow1 * 512 + bseg;
    const int sofs0 = brow0 * BPITCH + bseg * 16;
    const int sofs1 = brow1 * BPITCH + bseg * 16;

    // ldmatrix per-lane address part
    const int n_in = (lane & 7) | ((lane & 16) >> 1);
    const int lmoff = n_in * BPITCH + ((lane & 8) << 1);

    float C[8][4];
#pragma unroll
    for (int j = 0; j < 8; ++j)
#pragma unroll
        for (int i = 0; i < 4; ++i) C[j][i] = 0.0f;

    float2 Acur[16], Anext[16];
    uint4 pb[6];

    // prologue: chunk 0
#pragma unroll
    for (int ks = 0; ks < 4; ++ks) {
        Acur[ks * 4 + 0] = __ldcs(reinterpret_cast<const float2*>(xr0 + ks * 16 + qc));
        Acur[ks * 4 + 1] = __ldcs(reinterpret_cast<const float2*>(xr1 + ks * 16 + qc));
        Acur[ks * 4 + 2] = __ldcs(reinterpret_cast<const float2*>(xr0 + ks * 16 + qc + 8));
        Acur[ks * 4 + 3] = __ldcs(reinterpret_cast<const float2*>(xr1 + ks * 16 + qc + 8));
    }
    pb[0] = __ldg(pWh + bofs0); pb[1] = __ldg(pWh + bofs1);
    pb[2] = __ldg(pWm + bofs0); pb[3] = __ldg(pWm + bofs1);
    pb[4] = __ldg(pWl + bofs0); pb[5] = __ldg(pWl + bofs1);
    {
        char* b0 = smem;   // buffer 0
        *reinterpret_cast<uint4*>(b0 + 0 * LEVSZ + sofs0) = pb[0];
        *reinterpret_cast<uint4*>(b0 + 0 * LEVSZ + sofs1) = pb[1];
        *reinterpret_cast<uint4*>(b0 + 1 * LEVSZ + sofs0) = pb[2];
        *reinterpret_cast<uint4*>(b0 + 1 * LEVSZ + sofs1) = pb[3];
        *reinterpret_cast<uint4*>(b0 + 2 * LEVSZ + sofs0) = pb[4];
        *reinterpret_cast<uint4*>(b0 + 2 * LEVSZ + sofs1) = pb[5];
    }
    __syncthreads();

#pragma unroll 1
    for (int c = 0; c < NCHUNK; ++c) {
        // prefetch chunk c+1 (A to regs, B to regs)
        if (c + 1 < NCHUNK) {
            const int k1 = (c + 1) * KC;
#pragma unroll
            for (int ks = 0; ks < 4; ++ks) {
                Anext[ks * 4 + 0] = __ldcs(reinterpret_cast<const float2*>(xr0 + k1 + ks * 16 + qc));
                Anext[ks * 4 + 1] = __ldcs(reinterpret_cast<const float2*>(xr1 + k1 + ks * 16 + qc));
                Anext[ks * 4 + 2] = __ldcs(reinterpret_cast<const float2*>(xr0 + k1 + ks * 16 + qc + 8));
                Anext[ks * 4 + 3] = __ldcs(reinterpret_cast<const float2*>(xr1 + k1 + ks * 16 + qc + 8));
            }
            const size_t co = (size_t)(c + 1) * 8;
            pb[0] = __ldg(pWh + bofs0 + co); pb[1] = __ldg(pWh + bofs1 + co);
            pb[2] = __ldg(pWm + bofs0 + co); pb[3] = __ldg(pWm + bofs1 + co);
            pb[4] = __ldg(pWl + bofs0 + co); pb[5] = __ldg(pWl + bofs1 + co);
        }

        // compute chunk c from Acur + smem buffer (c&1)
        const uint32_t bb = sb + (uint32_t)(c & 1) * BUF3 + lmoff;
#pragma unroll
        for (int ks = 0; ks < 4; ++ks) {
            unsigned ah[4], am[4], al[4];
#pragma unroll
            for (int p = 0; p < 4; ++p)
                splitA(Acur[ks * 4 + p], ah[p], am[p], al[p]);

            unsigned bh[16], bm[16], bl[16];
#pragma unroll
            for (int p = 0; p < 4; ++p) {
                const uint32_t a0 = bb + p * (16 * BPITCH) + ks * 32;
                LDSM4(bh + 4 * p, a0 + 0 * LEVSZ);
                LDSM4(bm + 4 * p, a0 + 1 * LEVSZ);
                LDSM4(bl + 4 * p, a0 + 2 * LEVSZ);
            }
#pragma unroll
            for (int j = 0; j < 8; ++j) {
                MMA(C[j], ah, bh[2 * j], bh[2 * j + 1]);
                MMA(C[j], ah, bm[2 * j], bm[2 * j + 1]);
                MMA(C[j], am, bh[2 * j], bh[2 * j + 1]);
                MMA(C[j], am, bm[2 * j], bm[2 * j + 1]);
                MMA(C[j], ah, bl[2 * j], bl[2 * j + 1]);
                MMA(C[j], al, bh[2 * j], bh[2 * j + 1]);
            }
        }

        // publish chunk c+1
        if (c + 1 < NCHUNK) {
            char* bp = smem + ((c + 1) & 1) * BUF3;
            *reinterpret_cast<uint4*>(bp + 0 * LEVSZ + sofs0) = pb[0];
            *reinterpret_cast<uint4*>(bp + 0 * LEVSZ + sofs1) = pb[1];
            *reinterpret_cast<uint4*>(bp + 1 * LEVSZ + sofs0) = pb[2];
            *reinterpret_cast<uint4*>(bp + 1 * LEVSZ + sofs1) = pb[3];
            *reinterpret_cast<uint4*>(bp + 2 * LEVSZ + sofs0) = pb[4];
            *reinterpret_cast<uint4*>(bp + 2 * LEVSZ + sofs1) = pb[5];
#pragma unroll
            for (int i = 0; i < 16; ++i) Acur[i] = Anext[i];
        }
        __syncthreads();
    }

    // ---------------- epilogue ----------------
    float* s_imp = reinterpret_cast<float*>(smem);
    float* s_cnt = s_imp + NEXP;
    float* s_z   = s_cnt + NEXP;
    if (tid < NEXP) { s_imp[tid] = 0.0f; s_cnt[tid] = 0.0f; }
    if (tid == NEXP * 2) *s_z = 0.0f;   // any single thread; tid==128 exists
    __syncthreads();

    float v[16], p[16], imp[16];
    float zz = 0.0f;
#pragma unroll
    for (int i = 0; i < 16; ++i) imp[i] = 0.0f;

    // row g (c0,c1)
#pragma unroll
    for (int j = 0; j < 8; ++j) { v[2 * j] = C[j][0]; v[2 * j + 1] = C[j][1]; }
    row_epilogue(v, p, token_r0, qc, lane, out, s_cnt, zz);
#pragma unroll
    for (int i = 0; i < 16; ++i) imp[i] += p[i];

    // row g+8 (c2,c3)
#pragma unroll
    for (int j = 0; j < 8; ++j) { v[2 * j] = C[j][2]; v[2 * j + 1] = C[j][3]; }
    row_epilogue(v, p, token_r0 + 8, qc, lane, out, s_cnt, zz);
#pragma unroll
    for (int i = 0; i < 16; ++i) imp[i] += p[i];

    // reduce importance across the 8 row-groups (same lane&3)
#pragma unroll
    for (int o = 4; o <= 16; o <<= 1)
#pragma unroll
        for (int i = 0; i < 16; ++i)
            imp[i] += __shfl_xor_sync(0xffffffffu, imp[i], o);
    if (lane < 4) {
#pragma unroll
        for (int j = 0; j < 8; ++j) {
            atomicAdd(&s_imp[j * 8 + qc],     imp[2 * j]);
            atomicAdd(&s_imp[j * 8 + qc + 1], imp[2 * j + 1]);
        }
    }
    // z^2: sum across groups (lane&3 preserved), lane 0 commits
#pragma unroll
    for (int o = 4; o <= 16; o <<= 1) zz += __shfl_xor_sync(0xffffffffu, zz, o);
    if (lane == 0) atomicAdd(s_z, zz);
    __syncthreads();

    if (tid < NEXP) {
        atomicAdd(&g_acc[tid], s_imp[tid]);
        atomicAdd(&g_acc[NEXP + tid], s_cnt[tid]);
    }
    if (tid == NEXP * 2) atomicAdd(&g_acc[2 * NEXP], *s_z);

    // last CTA finalizes scalars
    __syncthreads();
    if (tid == 0) {
        __threadfence();
        unsigned prev = atomicAdd(&g_done, 1u);
        if (prev == NCTA - 1) {
#pragma unroll
            for (int i = 0; i < NEXP; ++i) {
                out[OFF_IMP + i]  = __ldcg(&g_acc[i]) * (1.0f / (float)NTOK);
                out[OFF_LOAD + i] = __ldcg(&g_acc[NEXP + i]) * (1.0f / (float)(2 * NTOK));
            }
            out[OFF_ZLOSS] = __ldcg(&g_acc[2 * NEXP]) * (1.0f / (float)NTOK);
        }
    }
}

// ---------------------------------------------------------------------------
extern "C" void kernel_launch(void* const* d_in, const int* in_sizes, int n_in,
                              void* d_out, int out_size) {
    const float* x = (const float*)d_in[0];   // [4,4096,4096] f32
    const float* W = (const float*)d_in[1];   // [64,4096] f32
    float* out = (float*)d_out;

    cudaFuncSetAttribute(router_kernel, cudaFuncAttributeMaxDynamicSharedMemorySize,
                         SMEM_TOTAL);

    prep_kernel<<<(NEXP * DDIM + 255) / 256, 256>>>(W);
    router_kernel<<<NCTA, THREADS, SMEM_TOTAL>>>(x, out);
}

// round 5
// speedup vs baseline: 2.7290x; 2.7290x over previous
#include <cuda_runtime.h>
#include <cuda_fp16.h>
#include <cstdint>

// Problem dims: B=4, S=4096, D=4096, E=64, K=2
#define NTOK 16384
#define DDIM 4096
#define NEXP 64
#define TPC  128                 // tokens per CTA
#define NCTA (NTOK / TPC)        // 128
#define THREADS 256
#define KC   64                  // K per chunk
#define NCHUNK (DDIM / KC)       // 64

// Output layout (flattened f32): idx[2N], scores[2N], probs[64N], zloss[1], imp[64], load[64]
#define OFF_IDX     0
#define OFF_SCORES  (NTOK * 2)
#define OFF_PROBS   (NTOK * 4)
#define OFF_ZLOSS   (NTOK * 4 + NTOK * NEXP)
#define OFF_IMP     (OFF_ZLOSS + 1)
#define OFF_LOAD    (OFF_IMP + NEXP)

// smem staging: A fp32 (pitch 72 floats = 288B -> 8-bank row offset, conflict-free
// LDS.64 quads) + B fp16 2 levels (pitch 144B, conflict-free ldmatrix)
#define APITCH 288
#define ASTAGE (TPC * APITCH)        // 36864
#define BPITCH 144
#define LEVSZ  (NEXP * BPITCH)       // 9216
#define BSTAGE (2 * LEVSZ)           // 18432
#define STAGE  (ASTAGE + BSTAGE)     // 55296
#define SMEM_TOTAL (2 * STAGE)       // 110592

#define SCALE   4096.0f              // 2^12 residual scaling
#define INVSCALE (1.0f / 4096.0f)

// Scratch globals
__device__ unsigned short g_Wh[NEXP * DDIM];
__device__ unsigned short g_Wl[NEXP * DDIM];   // fp16(2^12 * residual)
__device__ float g_acc[2 * NEXP + 1];
__device__ unsigned int g_done;

// ---------------------------------------------------------------------------
__device__ __forceinline__ uint32_t smem_u32(const void* p) {
    uint32_t a;
    asm("{ .reg .u64 t; cvta.to.shared.u64 t, %1; cvt.u32.u64 %0, t; }" : "=r"(a) : "l"(p));
    return a;
}

#define CPA16(sm, gp) \
    asm volatile("cp.async.cg.shared.global [%0], [%1], 16;" :: "r"(sm), "l"(gp))
#define CPC() asm volatile("cp.async.commit_group;" ::: "memory")
#define CPW1() asm volatile("cp.async.wait_group 1;" ::: "memory")
#define CPW0() asm volatile("cp.async.wait_group 0;" ::: "memory")

#define LDSM4(R, a) \
    asm volatile("ldmatrix.sync.aligned.m8n8.x4.shared.b16 {%0,%1,%2,%3}, [%4];" \
        : "=r"((R)[0]), "=r"((R)[1]), "=r"((R)[2]), "=r"((R)[3]) : "r"(a))

#define MMA(C, A, B0, B1) \
    asm volatile("mma.sync.aligned.m16n8k16.row.col.f32.f16.f16.f32 " \
        "{%0,%1,%2,%3}, {%4,%5,%6,%7}, {%8,%9}, {%0,%1,%2,%3};" \
        : "+f"((C)[0]), "+f"((C)[1]), "+f"((C)[2]), "+f"((C)[3]) \
        : "r"((A)[0]), "r"((A)[1]), "r"((A)[2]), "r"((A)[3]), "r"(B0), "r"(B1))

// split float2 -> fp16x2 high + fp16x2 of 2^12*residual
__device__ __forceinline__ void splitAx(float2 v, unsigned& h, unsigned& l) {
    __half2 hh = __float22half2_rn(v);
    float2 back = __half22float2(hh);
    float2 r = make_float2((v.x - back.x) * SCALE, (v.y - back.y) * SCALE);
    __half2 ll = __float22half2_rn(r);
    h = *reinterpret_cast<unsigned*>(&hh);
    l = *reinterpret_cast<unsigned*>(&ll);
}

__device__ __forceinline__ bool better(float v1, int i1, float v2, int i2) {
    return (v1 > v2) || (v1 == v2 && i1 < i2);
}

// ---------------------------------------------------------------------------
// Kernel 1: split W into fp16 high + scaled-residual levels; zero accumulators
// ---------------------------------------------------------------------------
__global__ void prep_kernel(const float* __restrict__ W) {
    int i = blockIdx.x * 256 + threadIdx.x;
    if (i < NEXP * DDIM) {
        float w = W[i];
        __half h = __float2half_rn(w);
        float r = (w - __half2float(h)) * SCALE;
        __half l = __float2half_rn(r);
        g_Wh[i] = *reinterpret_cast<unsigned short*>(&h);
        g_Wl[i] = *reinterpret_cast<unsigned short*>(&l);
    }
    if (i < 2 * NEXP + 1) g_acc[i] = 0.0f;
    if (i == 0) g_done = 0u;
}

// ---------------------------------------------------------------------------
// per-token-row routing epilogue (quad of 4 lanes owns one row of 64 logits)
// ---------------------------------------------------------------------------
__device__ __forceinline__ void row_epilogue(const float v[16], float p[16],
                                             int token, int qc, int lane,
                                             float* __restrict__ out,
                                             float* s_cnt, float& zz) {
    float mx = v[0];
#pragma unroll
    for (int i = 1; i < 16; ++i) mx = fmaxf(mx, v[i]);
    mx = fmaxf(mx, __shfl_xor_sync(0xffffffffu, mx, 1));
    mx = fmaxf(mx, __shfl_xor_sync(0xffffffffu, mx, 2));
    float s = 0.0f;
#pragma unroll
    for (int i = 0; i < 16; ++i) { p[i] = __expf(v[i] - mx); s += p[i]; }
    s += __shfl_xor_sync(0xffffffffu, s, 1);
    s += __shfl_xor_sync(0xffffffffu, s, 2);
    const float inv = 1.0f / s;
#pragma unroll
    for (int i = 0; i < 16; ++i) p[i] *= inv;
    float* po = out + OFF_PROBS + (size_t)token * NEXP;
#pragma unroll
    for (int j = 0; j < 8; ++j)
        *reinterpret_cast<float2*>(po + j * 8 + qc) = make_float2(p[2 * j], p[2 * j + 1]);
    // local top-2 (ascending col order; strict > keeps lowest index on ties)
    float av = -3.4e38f, bv = -3.4e38f; int ai = 0, bi = 0;
#pragma unroll
    for (int j = 0; j < 8; ++j)
#pragma unroll
        for (int i = 0; i < 2; ++i) {
            float val = v[j * 2 + i];
            int col = j * 8 + qc + i;
            if (val > av)      { bv = av; bi = ai; av = val; ai = col; }
            else if (val > bv) { bv = val; bi = col; }
        }
#pragma unroll
    for (int o = 1; o <= 2; o <<= 1) {
        float av2 = __shfl_xor_sync(0xffffffffu, av, o);
        int   ai2 = __shfl_xor_sync(0xffffffffu, ai, o);
        float bv2 = __shfl_xor_sync(0xffffffffu, bv, o);
        int   bi2 = __shfl_xor_sync(0xffffffffu, bi, o);
        if (better(av2, ai2, av, ai)) {
            bool s2 = better(bv2, bi2, av, ai);
            float nbv = s2 ? bv2 : av; int nbi = s2 ? bi2 : ai;
            av = av2; ai = ai2; bv = nbv; bi = nbi;
        } else if (better(av2, ai2, bv, bi)) { bv = av2; bi = ai2; }
    }
    if ((lane & 3) == 0) {
        float ex  = __expf(bv - av);
        float sc0 = 1.0f / (1.0f + ex);
        out[OFF_IDX + token * 2]        = (float)ai;
        out[OFF_IDX + token * 2 + 1]    = (float)bi;
        out[OFF_SCORES + token * 2]     = sc0;
        out[OFF_SCORES + token * 2 + 1] = ex * sc0;
        atomicAdd(&s_cnt[ai], 1.0f);
        atomicAdd(&s_cnt[bi], 1.0f);
    }
    float z = mx + __logf(s);
    zz += z * z;
}

// ---------------------------------------------------------------------------
// Kernel 2: fused 3-way fp16-split GEMM (mma.sync) + routing epilogue.
// cp.async 2-stage pipeline stages A (fp32) and both W levels per 64-K chunk.
// ---------------------------------------------------------------------------
__global__ void __launch_bounds__(THREADS, 1)
router_kernel(const float* __restrict__ x, float* __restrict__ out) {
    extern __shared__ __align__(16) char smem[];
    const uint32_t sb = smem_u32(smem);
    const int tid = threadIdx.x, w = tid >> 5, lane = tid & 31;
    const int g = lane >> 2, q = lane & 3, qc = q * 2;
    const int token0 = blockIdx.x * TPC;

    // ---- cp.async source/dest mappings ----
    // A: 2048 16B segs/stage, 8 per thread. row = idx>>4, seg = idx&15.
    const char* xbytes = reinterpret_cast<const char*>(x);
    // B: 1024 16B segs/stage (2 levels x 64 rows x 8), 4 per thread.
    const char* whb = reinterpret_cast<const char*>(g_Wh);
    const char* wlb = reinterpret_cast<const char*>(g_Wl);

    // ldmatrix per-lane address component (proven layout from prior round)
    const int n_in = (lane & 7) | ((lane & 16) >> 1);
    const int lmoff = n_in * BPITCH + ((lane & 8) << 1);

    // A fragment smem addresses for this warp (rows w*16+g and +8)
    const uint32_t arow0 = sb + (uint32_t)(w * 16 + g) * APITCH + (uint32_t)qc * 4;
    const uint32_t arow1 = arow0 + 8u * APITCH;

    float C[8][4], Clo[8][4];
#pragma unroll
    for (int j = 0; j < 8; ++j)
#pragma unroll
        for (int i = 0; i < 4; ++i) { C[j][i] = 0.0f; Clo[j][i] = 0.0f; }

    // ---- issue stage 0 ----
    {
        const uint32_t sa = sb;                 // stage 0 A base
        const uint32_t sbB = sb + ASTAGE;       // stage 0 B base
#pragma unroll
        for (int ps = 0; ps < 8; ++ps) {
            int idx = tid + ps * 256;
            int row = idx >> 4, seg = idx & 15;
            CPA16(sa + row * APITCH + seg * 16,
                  xbytes + ((size_t)(token0 + row) * DDIM + seg * 4) * 4);
        }
#pragma unroll
        for (int ps = 0; ps < 4; ++ps) {
            int idx = tid + ps * 256;
            int lev = idx >> 9, rem = idx & 511, row = rem >> 3, seg = rem & 7;
            const char* src = (lev == 0 ? whb : wlb) + ((size_t)row * DDIM + seg * 8) * 2;
            CPA16(sbB + lev * LEVSZ + row * BPITCH + seg * 16, src);
        }
        CPC();
    }

#pragma unroll 1
    for (int c = 0; c < NCHUNK; ++c) {
        // ---- issue stage c+1 into the other buffer ----
        if (c + 1 < NCHUNK) {
            const int k1 = (c + 1) * KC;
            const uint32_t stg = sb + (uint32_t)((c + 1) & 1) * STAGE;
            const uint32_t sbB = stg + ASTAGE;
#pragma unroll
            for (int ps = 0; ps < 8; ++ps) {
                int idx = tid + ps * 256;
                int row = idx >> 4, seg = idx & 15;
                CPA16(stg + row * APITCH + seg * 16,
                      xbytes + ((size_t)(token0 + row) * DDIM + k1 + seg * 4) * 4);
            }
#pragma unroll
            for (int ps = 0; ps < 4; ++ps) {
                int idx = tid + ps * 256;
                int lev = idx >> 9, rem = idx & 511, row = rem >> 3, seg = rem & 7;
                const char* src = (lev == 0 ? whb : wlb) + ((size_t)row * DDIM + k1 + seg * 8) * 2;
                CPA16(sbB + lev * LEVSZ + row * BPITCH + seg * 16, src);
            }
            CPC();
            CPW1();           // stage c complete
        } else {
            CPW0();
        }
        __syncthreads();

        // ---- consume stage c ----
        const uint32_t stg = sb + (uint32_t)(c & 1) * STAGE;
        const uint32_t a0 = arow0 + (uint32_t)(c & 1) * STAGE;
        const uint32_t a1 = arow1 + (uint32_t)(c & 1) * STAGE;
        const uint32_t bbase = stg + ASTAGE + lmoff;

#pragma unroll
        for (int ks = 0; ks < 4; ++ks) {
            // A fragments from smem (+ split)
            float2 f0, f1, f2, f3;
            const uint32_t ka = (uint32_t)(ks * 64);
            asm volatile("ld.shared.v2.f32 {%0,%1}, [%2];" : "=f"(f0.x), "=f"(f0.y) : "r"(a0 + ka));
            asm volatile("ld.shared.v2.f32 {%0,%1}, [%2];" : "=f"(f1.x), "=f"(f1.y) : "r"(a1 + ka));
            asm volatile("ld.shared.v2.f32 {%0,%1}, [%2];" : "=f"(f2.x), "=f"(f2.y) : "r"(a0 + ka + 32));
            asm volatile("ld.shared.v2.f32 {%0,%1}, [%2];" : "=f"(f3.x), "=f"(f3.y) : "r"(a1 + ka + 32));
            unsigned ah[4], al[4];
            splitAx(f0, ah[0], al[0]);
            splitAx(f1, ah[1], al[1]);
            splitAx(f2, ah[2], al[2]);
            splitAx(f3, ah[3], al[3]);

#pragma unroll
            for (int p = 0; p < 4; ++p) {
                const uint32_t ba = bbase + p * (16 * BPITCH) + ks * 32;
                unsigned bh[4], bl[4];
                LDSM4(bh, ba);
                LDSM4(bl, ba + LEVSZ);
                const int j0 = 2 * p, j1 = 2 * p + 1;
                MMA(C[j0],   ah, bh[0], bh[1]);
                MMA(C[j1],   ah, bh[2], bh[3]);
                MMA(Clo[j0], ah, bl[0], bl[1]);
                MMA(Clo[j1], ah, bl[2], bl[3]);
                MMA(Clo[j0], al, bh[0], bh[1]);
                MMA(Clo[j1], al, bh[2], bh[3]);
            }
        }
        __syncthreads();   // all reads of stage c done before it is overwritten
    }

    // ---------------- epilogue ----------------
    float* s_imp = reinterpret_cast<float*>(smem);
    float* s_cnt = s_imp + NEXP;
    float* s_z   = s_cnt + NEXP;
    if (tid < NEXP) { s_imp[tid] = 0.0f; s_cnt[tid] = 0.0f; }
    if (tid == NEXP * 2) *s_z = 0.0f;
    __syncthreads();

    const int token_r0 = token0 + w * 16 + g;
    float v[16], p[16], imp[16];
    float zz = 0.0f;
#pragma unroll
    for (int i = 0; i < 16; ++i) imp[i] = 0.0f;

    // row g (C lanes 0,1)
#pragma unroll
    for (int j = 0; j < 8; ++j) {
        v[2 * j]     = fmaf(Clo[j][0], INVSCALE, C[j][0]);
        v[2 * j + 1] = fmaf(Clo[j][1], INVSCALE, C[j][1]);
    }
    row_epilogue(v, p, token_r0, qc, lane, out, s_cnt, zz);
#pragma unroll
    for (int i = 0; i < 16; ++i) imp[i] += p[i];

    // row g+8 (C lanes 2,3)
#pragma unroll
    for (int j = 0; j < 8; ++j) {
        v[2 * j]     = fmaf(Clo[j][2], INVSCALE, C[j][2]);
        v[2 * j + 1] = fmaf(Clo[j][3], INVSCALE, C[j][3]);
    }
    row_epilogue(v, p, token_r0 + 8, qc, lane, out, s_cnt, zz);
#pragma unroll
    for (int i = 0; i < 16; ++i) imp[i] += p[i];

    // importance across the 8 row-groups (same lane&3)
#pragma unroll
    for (int o = 4; o <= 16; o <<= 1)
#pragma unroll
        for (int i = 0; i < 16; ++i)
            imp[i] += __shfl_xor_sync(0xffffffffu, imp[i], o);
    if (lane < 4) {
#pragma unroll
        for (int j = 0; j < 8; ++j) {
            atomicAdd(&s_imp[j * 8 + qc],     imp[2 * j]);
            atomicAdd(&s_imp[j * 8 + qc + 1], imp[2 * j + 1]);
        }
    }
#pragma unroll
    for (int o = 4; o <= 16; o <<= 1) zz += __shfl_xor_sync(0xffffffffu, zz, o);
    if (lane == 0) atomicAdd(s_z, zz);
    __syncthreads();

    if (tid < NEXP) {
        atomicAdd(&g_acc[tid], s_imp[tid]);
        atomicAdd(&g_acc[NEXP + tid], s_cnt[tid]);
    }
    if (tid == NEXP * 2) atomicAdd(&g_acc[2 * NEXP], *s_z);

    __syncthreads();
    if (tid == 0) {
        __threadfence();
        unsigned prev = atomicAdd(&g_done, 1u);
        if (prev == NCTA - 1) {
#pragma unroll
            for (int i = 0; i < NEXP; ++i) {
                out[OFF_IMP + i]  = __ldcg(&g_acc[i]) * (1.0f / (float)NTOK);
                out[OFF_LOAD + i] = __ldcg(&g_acc[NEXP + i]) * (1.0f / (float)(2 * NTOK));
            }
            out[OFF_ZLOSS] = __ldcg(&g_acc[2 * NEXP]) * (1.0f / (float)NTOK);
        }
    }
}

// ---------------------------------------------------------------------------
extern "C" void kernel_launch(void* const* d_in, const int* in_sizes, int n_in,
                              void* d_out, int out_size) {
    const float* x = (const float*)d_in[0];   // [4,4096,4096] f32
    const float* W = (const float*)d_in[1];   // [64,4096] f32
    float* out = (float*)d_out;

    cudaFuncSetAttribute(router_kernel, cudaFuncAttributeMaxDynamicSharedMemorySize,
                         SMEM_TOTAL);

    prep_kernel<<<(NEXP * DDIM + 255) / 256, 256>>>(W);
    router_kernel<<<NCTA, THREADS, SMEM_TOTAL>>>(x, out);
}